// round 10
// baseline (speedup 1.0000x reference)
#include <cuda_runtime.h>

#define NN 2048
#define FEAT 64
#define HID 16
#define C 8
#define NG 64
#define MAXSEG 128     // hard bound: sum ceil(len_g/32) <= 64 + 64

// scratch (allocation-free rule: device globals)
__device__ __align__(16) float g_node[NN * C];   // per-node summed feature MLP
__device__ __align__(16) float e_tab[11 * C];    // rho-MLP table for dist = 0..10
__device__ int d_seg_start[MAXSEG];
__device__ int d_seg_len[MAXSEG];
__device__ int d_seg_graph[MAXSEG];
__device__ int d_nseg;

// ---------------------------------------------------------------------------
// Kernel 1 (v2): g[n,c] = sum_f ( sum_h relu(x[n,f]*w1[f,h]+b1[f,h]) * w2[f,h,c] + b2[f,c] )
// 64 blocks x 256 threads; block = 32 nodes. lane = node, warp = 8 features.
// ALL weight loads are warp-uniform (1 wavefront, L1 broadcast); x comes from
// a padded smem tile (conflict-free). Fixes the 512B-lane-stride w2 loads
// that made v1 L1tex-wavefront-bound (~32 lines per LDG).
// Block 0 additionally: e-table, d_out zeroing, parallel segment build.
// ---------------------------------------------------------------------------
__global__ void __launch_bounds__(256) tgnan_k1(
    const float* __restrict__ x,
    const int*   __restrict__ batch,
    const float* __restrict__ w1, const float* __restrict__ b1,
    const float* __restrict__ w2, const float* __restrict__ b2,
    const float* __restrict__ rw1, const float* __restrict__ rb1,
    const float* __restrict__ rw2, const float* __restrict__ rb2,
    float* __restrict__ out)
{
    __shared__ float x_s[32 * 65];            // 32 nodes x 64 feats, pad 1
    __shared__ float ps[8][32][C];            // per-warp partial sums

    const int tid  = threadIdx.x;
    const int wid  = tid >> 5;                // 0..7  (feature slice)
    const int lane = tid & 31;                // node within block
    const int n0   = blockIdx.x * 32;

    // stage x tile, coalesced
#pragma unroll
    for (int i = tid; i < 32 * 64; i += 256) {
        const int r = i >> 6, cc = i & 63;
        x_s[r * 65 + cc] = __ldg(x + (size_t)(n0 + r) * FEAT + cc);
    }
    __syncthreads();

    float acc[C];
#pragma unroll
    for (int c = 0; c < C; c++) acc[c] = 0.0f;

#pragma unroll
    for (int k = 0; k < 8; k++) {
        const int f = wid * 8 + k;            // warp-uniform feature index
        const float xv = x_s[lane * 65 + f];  // conflict-free (260B stride)
        const float4* b2p = reinterpret_cast<const float4*>(b2 + f * C);
        const float4 b2a = __ldg(b2p);
        const float4 b2b = __ldg(b2p + 1);
        acc[0] += b2a.x; acc[1] += b2a.y; acc[2] += b2a.z; acc[3] += b2a.w;
        acc[4] += b2b.x; acc[5] += b2b.y; acc[6] += b2b.z; acc[7] += b2b.w;
#pragma unroll
        for (int h = 0; h < HID; h++) {
            const float hv = fmaxf(fmaf(xv, __ldg(w1 + f * HID + h),
                                        __ldg(b1 + f * HID + h)), 0.0f);
            const float4* wp = reinterpret_cast<const float4*>(w2 + (size_t)(f * HID + h) * C);
            const float4 wa = __ldg(wp);      // warp-uniform 32B
            const float4 wb = __ldg(wp + 1);
            acc[0] = fmaf(hv, wa.x, acc[0]);
            acc[1] = fmaf(hv, wa.y, acc[1]);
            acc[2] = fmaf(hv, wa.z, acc[2]);
            acc[3] = fmaf(hv, wa.w, acc[3]);
            acc[4] = fmaf(hv, wb.x, acc[4]);
            acc[5] = fmaf(hv, wb.y, acc[5]);
            acc[6] = fmaf(hv, wb.z, acc[6]);
            acc[7] = fmaf(hv, wb.w, acc[7]);
        }
    }
#pragma unroll
    for (int c = 0; c < C; c++) ps[wid][lane][c] = acc[c];
    __syncthreads();

    // final: 256 threads, one (node, channel) each; coalesced g_node store
    {
        const int n = tid >> 3, c = tid & 7;
        float s = 0.0f;
#pragma unroll
        for (int ww = 0; ww < 8; ww++) s += ps[ww][n][c];
        g_node[(size_t)(n0 + n) * C + c] = s;
    }

    if (blockIdx.x == 0) {
        // ---- e-table: rho MLP at dist = 0..10 (dist = -1 contributes 0) ----
        if (tid < 11) {
            const float dd = (float)tid;
            float a2[C];
#pragma unroll
            for (int c = 0; c < C; c++) a2[c] = rb2[c];
#pragma unroll
            for (int h = 0; h < HID; h++) {
                const float hv = fmaxf(fmaf(dd, rw1[h], rb1[h]), 0.0f);
#pragma unroll
                for (int c = 0; c < C; c++)
                    a2[c] = fmaf(hv, rw2[h * C + c], a2[c]);
            }
#pragma unroll
            for (int c = 0; c < C; c++) e_tab[tid * C + c] = a2[c];
        }
        // ---- zero output (d_out is poisoned; k2 accumulates atomically) ----
        for (int i = tid; i < NG * C; i += 256) out[i] = 0.0f;

        // ---- parallel segment build (order-independent slot allocation) ----
        __shared__ int bstart[NG + 1];
        __shared__ int nseg_s;
        if (tid <= NG) bstart[tid] = (tid == NG) ? NN : -1;
        if (tid == 0) nseg_s = 0;
        __syncthreads();
        if (tid < 64) {                       // thread scans 32 rows
            const int r0 = tid * 32;
            int prev = (r0 == 0) ? -1 : __ldg(batch + r0 - 1);
            for (int i = 0; i < 32; i++) {
                const int b = __ldg(batch + r0 + i);
                if (b != prev) bstart[b] = r0 + i;   // unique writer per graph
                prev = b;
            }
        }
        __syncthreads();
        if (tid < NG) {                       // thread = graph: emit segments
            const int s = bstart[tid];
            if (s >= 0) {
                int e = NN;
                for (int g2 = tid + 1; g2 <= NG; g2++) {
                    if (bstart[g2] >= 0) { e = bstart[g2]; break; }
                }
                const int len = e - s;
                const int ns  = (len + 31) >> 5;
                const int off = atomicAdd(&nseg_s, ns);
                for (int i = 0; i < ns; i++) {
                    d_seg_start[off + i] = s + i * 32;
                    d_seg_len[off + i]   = min(32, len - i * 32);
                    d_seg_graph[off + i] = tid;
                }
            }
        }
        __syncthreads();
        if (tid == 0) d_nseg = nseg_s;
    }
}

// ---------------------------------------------------------------------------
// Kernel 2: out[b,c] += sum_m g[m,c] * sum_{n in segment} e[dist(n,m), c]
// Block = 256 thr = 8 warps. blockIdx.x = m-group (8 warps x 32 cols = 256 m),
// blockIdx.y = segment. Hot loop: 32 predicated LDGs (padding -> dist=-1 ->
// bucket 0 -> contributes 0), batched 16 deep; 12x10-bit 2xu64 histogram.
// Emit once per task; block-level reduce -> 8 atomics per block.
// ---------------------------------------------------------------------------
__global__ void __launch_bounds__(256) tgnan_k2(
    const float* __restrict__ dist,
    float* __restrict__ out)
{
    __shared__ float er_s[11][C];
    __shared__ float bp[8][C];
    if (threadIdx.x < 11 * C) ((float*)er_s)[threadIdx.x] = e_tab[threadIdx.x];
    __syncthreads();

    const int seg = blockIdx.y;
    if (seg >= d_nseg) return;               // block-uniform exit

    const int wid  = threadIdx.x >> 5;       // 0..7
    const int lane = threadIdx.x & 31;
    const int m    = (blockIdx.x * 8 + wid) * 32 + lane;
    const int start = d_seg_start[seg];
    const int len   = d_seg_len[seg];
    const int gb    = d_seg_graph[seg];

    const float* pd = dist + (size_t)start * NN + m;

    unsigned long long h0 = 0ull, h1 = 0ull; // buckets 0..5 / 6..11, 10-bit fields
#pragma unroll
    for (int half = 0; half < 2; half++) {
        float fd[16];
#pragma unroll
        for (int i = 0; i < 16; i++) {       // 16 independent predicated LDGs
            const int r = half * 16 + i;
            fd[i] = (r < len) ? __ldg(pd + (size_t)r * NN) : -1.0f;
        }
#pragma unroll
        for (int i = 0; i < 16; i++) {
            int di = (int)fd[i] + 1;         // -1..10 -> 0..11 (exact ints)
            di = max(0, min(11, di));
            const bool hi = di >= 6;
            const unsigned long long inc = 1ull << (10 * (hi ? di - 6 : di));
            if (hi) h1 += inc; else h0 += inc;
        }
    }

    // emit: p[c] = (sum_d cnt_d * e[d,c]) * g[m,c]
    float p[C];
#pragma unroll
    for (int c = 0; c < C; c++) p[c] = 0.0f;
#pragma unroll
    for (int d = 1; d < 12; d++) {           // bucket 0 (dist=-1) contributes 0
        const unsigned int cnt = (unsigned int)
            ((d < 6 ? (h0 >> (10 * d)) : (h1 >> (10 * (d - 6)))) & 1023u);
        const float fc = (float)cnt;
#pragma unroll
        for (int c = 0; c < C; c++)
            p[c] = fmaf(fc, er_s[d - 1][c], p[c]);
    }
    {
        const float4* gp = reinterpret_cast<const float4*>(g_node + (size_t)m * C);
        const float4 ga = gp[0];
        const float4 gb4 = gp[1];
        p[0] *= ga.x;  p[1] *= ga.y;  p[2] *= ga.z;  p[3] *= ga.w;
        p[4] *= gb4.x; p[5] *= gb4.y; p[6] *= gb4.z; p[7] *= gb4.w;
    }
#pragma unroll
    for (int off = 16; off; off >>= 1)
#pragma unroll
        for (int c = 0; c < C; c++)
            p[c] += __shfl_xor_sync(0xffffffffu, p[c], off);

    if (lane == 0) {
#pragma unroll
        for (int c = 0; c < C; c++) bp[wid][c] = p[c];
    }
    __syncthreads();
    if (threadIdx.x < C) {
        float s = 0.0f;
#pragma unroll
        for (int ww = 0; ww < 8; ww++) s += bp[ww][threadIdx.x];
        atomicAdd(out + gb * C + threadIdx.x, s);
    }
}

// ---------------------------------------------------------------------------
extern "C" void kernel_launch(void* const* d_in, const int* in_sizes, int n_in,
                              void* d_out, int out_size)
{
    const float* x    = (const float*)d_in[0];
    const float* dist = (const float*)d_in[1];
    const int*   bv   = (const int*)d_in[2];
    const float* fw1  = (const float*)d_in[3];
    const float* fb1  = (const float*)d_in[4];
    const float* fw2  = (const float*)d_in[5];
    const float* fb2  = (const float*)d_in[6];
    const float* rw1  = (const float*)d_in[7];
    const float* rb1  = (const float*)d_in[8];
    const float* rw2  = (const float*)d_in[9];
    const float* rb2  = (const float*)d_in[10];
    float* out = (float*)d_out;

    tgnan_k1<<<NG, 256>>>(x, bv, fw1, fb1, fw2, fb2, rw1, rb1, rw2, rb2, out);
    dim3 g2(8, MAXSEG, 1);                   // 8 m-groups x up to 128 segments
    tgnan_k2<<<g2, 256>>>(dist, out);
}